// round 15
// baseline (speedup 1.0000x reference)
#include <cuda_runtime.h>
#include <math.h>

#define NN 256
#define NM 240
#define NB 120
#define ITERS 30
#define PER_LAUNCH (2 * NB)

typedef unsigned long long u64;
union F2 { u64 u; float2 f; };
#define ONES2 0x3f8000003f800000ULL

// ---------------- device scratch ----------------
__device__ float4   g_At4[60 * NM];    // [kb*240+j] = A[j][16+4kb..16+4kb+3]
__device__ float4   g_Ab4[60 * NM];    // [jb*240+k] = A[4jb+r][16+k]
__device__ float    g_S2buf[4][256];   // 4-slot tau-grad accumulators
__device__ float    g_Lbuf[4];         // 4-slot loss accumulators
__device__ float    g_Lp[128];         // epilogue per-block loss partials
__device__ unsigned g_gc[4];           // per-slot head-arrival counters (monotonic)
__device__ unsigned g_barcnt;          // for the 2 real grid barriers

// ---------------- helpers ----------------
static __device__ __forceinline__ unsigned ld_acq(const unsigned* p) {
    unsigned v; asm volatile("ld.acquire.gpu.global.u32 %0,[%1];" : "=r"(v) : "l"(p)); return v;
}
static __device__ __forceinline__ float ldcg(const float* p) {
    float v; asm volatile("ld.global.cg.f32 %0,[%1];" : "=f"(v) : "l"(p)); return v;
}
static __device__ __forceinline__ float4 ldcg4(const float4* p) {
    float4 v;
    asm volatile("ld.global.cg.v4.f32 {%0,%1,%2,%3},[%4];"
                 : "=f"(v.x), "=f"(v.y), "=f"(v.z), "=f"(v.w) : "l"(p));
    return v;
}
static __device__ __forceinline__ void redadd(float* p, float v) {
    asm volatile("red.global.add.f32 [%0],%1;" :: "l"(p), "f"(v) : "memory");
}
static __device__ __forceinline__ float rcpa(float x) {
    float r; asm("rcp.approx.f32 %0,%1;" : "=f"(r) : "f"(x)); return r;
}
static __device__ __forceinline__ u64 fma2_(u64 a, u64 b, u64 c) {
    u64 d; asm("fma.rn.f32x2 %0,%1,%2,%3;" : "=l"(d) : "l"(a), "l"(b), "l"(c)); return d;
}
static __device__ __forceinline__ u64 mul2_(u64 a, u64 b) {
    u64 d; asm("mul.rn.f32x2 %0,%1,%2;" : "=l"(d) : "l"(a), "l"(b)); return d;
}
static __device__ __forceinline__ float sigm(float x) { return 1.0f / (1.0f + __expf(-x)); }

#define WRED(val, dst) do { float _v = (val);                             \
    _v += __shfl_down_sync(0xffffffffu, _v, 16);                          \
    _v += __shfl_down_sync(0xffffffffu, _v, 8);                           \
    _v += __shfl_down_sync(0xffffffffu, _v, 4);                           \
    _v += __shfl_down_sync(0xffffffffu, _v, 2);                          \
    _v += __shfl_down_sync(0xffffffffu, _v, 1);                          \
    if ((tx & 31) == 0) (dst)[tx >> 5] = _v; } while (0)

static __device__ __forceinline__ float sum8(const float* w, int g) {
    float s = 0.f;
    #pragma unroll
    for (int i = 0; i < 8; ++i) s += w[g * 8 + i];
    return s;
}

#define GRIDBAR() do { __syncthreads();                                   \
    if (tx == 0) { __threadfence(); atomicAdd(&g_barcnt, 1u);             \
        while (ld_acq(&g_barcnt) < bartgt) __nanosleep(32); }             \
    bartgt += NB; __syncthreads(); } while (0)

#define QUADACC(t01u, t23u, n01u, n23u, acc, bad) do {                    \
    F2 _t0; _t0.u = (t01u); F2 _t1; _t1.u = (t23u);                       \
    F2 _n0; _n0.u = (n01u); F2 _n1; _n1.u = (n23u);                       \
    float _P01 = _t0.f.x * _t0.f.y;                                       \
    float _P23 = _t1.f.x * _t1.f.y;                                       \
    float _T = _P01 * _P23;                                               \
    float _r = rcpa(_T);                                                  \
    float _m1 = fmaf(_n0.f.y, _t0.f.x, _n0.f.x * _t0.f.y);                \
    float _m3 = fmaf(_n1.f.y, _t1.f.x, _n1.f.x * _t1.f.y);                \
    float _s = fmaf(_m3, _P01, _m1 * _P23);                               \
    bool _ok = (_T != 0.f);                                               \
    acc += _ok ? _s * _r : 0.f;                                           \
    bad |= !_ok; } while (0)

// ---------------- persistent kernel ----------------
__global__ void __launch_bounds__(1024, 1) gflow(
    const float* __restrict__ A, const float* __restrict__ Gl0,
    const float* __restrict__ tau0, float* __restrict__ out)
{
    const int b  = blockIdx.x;
    const int tx = threadIdx.x;
    const int Q  = tx >> 8;
    const int U  = tx & 255;
    const int r0 = b, r1 = b + NB;

    __shared__ u64   GnaP[120], GnbP[120];
    __shared__ float4 DsA4[60], DsB4[60];
    __shared__ float pfA[4 * NM], pfB[4 * NM];
    __shared__ float taus[NN];
    __shared__ float msh[NN], vsh[NN];
    __shared__ float wsum[32], wsum2[32];
    __shared__ float lsh;
    float* GnaF = (float*)GnaP;
    float* GnbF = (float*)GnbP;
    const ulonglong2* At8  = (const ulonglong2*)g_At4;
    const ulonglong2* Ab8  = (const ulonglong2*)g_Ab4;
    const ulonglong2* DsA8 = (const ulonglong2*)DsA4;
    const ulonglong2* DsB8 = (const ulonglong2*)DsB4;
    const ulonglong2* GnaP2 = (const ulonglong2*)GnaP;
    const ulonglong2* GnbP2 = (const ulonglong2*)GnbP;

    unsigned bartgt = (ld_acq(&g_barcnt) / PER_LAUNCH) * PER_LAUNCH + NB;
    // per-slot launch bases; counters are EXACT multiples at launch start
    // (slot s receives {8,8,7,7}[s] * 120 arrivals per launch)
    unsigned gbase[4];
    gbase[0] = (ld_acq(&g_gc[0]) / 960u) * 960u;
    gbase[1] = (ld_acq(&g_gc[1]) / 960u) * 960u;
    gbase[2] = (ld_acq(&g_gc[2]) / 840u) * 840u;
    gbase[3] = (ld_acq(&g_gc[3]) / 840u) * 840u;

    // ---- init: repack A (both layouts), zero slots, load params ----
    if (tx < 120) {
        int e = b * 120 + tx, kb = e / NM, j = e % NM;
        g_At4[e] = *(const float4*)(A + j * NN + 16 + 4 * kb);
        float4 v;
        v.x = A[(4 * kb + 0) * NN + 16 + j];
        v.y = A[(4 * kb + 1) * NN + 16 + j];
        v.z = A[(4 * kb + 2) * NN + 16 + j];
        v.w = A[(4 * kb + 3) * NN + 16 + j];
        g_Ab4[e] = v;
    }
    if (b == 0) {
        if (tx < 1024) ((float*)g_S2buf)[tx] = 0.f;
        if (tx < 4) g_Lbuf[tx] = 0.f;
    }
    float gl = 0.f, mg = 0.f, vg = 0.f;
    if (Q < 2 && U < NM) gl = Gl0[(Q ? r1 : r0) * NM + U];
    if (tx < NN) { taus[tx] = tau0[tx]; msh[tx] = 0.f; vsh[tx] = 0.f; }
    GRIDBAR();  // barrier #1

    double b1t = 1.0, b2t = 1.0;
    float bc1p = 1.f, bc2p = 1.f;
    int stop = 0;

    for (int t = 0; t < ITERS; ++t) {
        b1t *= 0.9; b2t *= 0.999;
        const float bc1c = (float)(1.0 / (1.0 - b1t));
        const float bc2c = (float)(1.0 / (1.0 - b2t));
        const int cs = t & 3;          // write slot
        const int zs = (t + 1) & 3;    // zero slot (readers finished at head t-1)
        float sreg = 0.f;

        // ================= HEAD =================
        if (t > 0) {
            const int ws = (t - 1) & 3;    // S2 read slot (lag 1)
            unsigned tgt = gbase[ws] + ((unsigned)((t - 1) >> 2) + 1u) * 120u;
            if (tx == 0) { while (ld_acq(&g_gc[ws]) < tgt) __nanosleep(32); }
            __syncthreads();   // broadcast acquire
            float s2v = 0.f;
            if (tx < 256) s2v = ldcg(&g_S2buf[ws][tx]);      // READ ONLY
            if (t >= 2 && tx == 0) lsh = ldcg(&g_Lbuf[(t - 2) & 3]);  // READ ONLY
            if (!stop && tx < 256) {   // tau Adam, step t-1
                float g = -(2.f / 61440.f) * s2v;
                float mm = 0.9f * msh[tx] + 0.1f * g;
                float vv = 0.999f * vsh[tx] + 0.001f * g * g;
                msh[tx] = mm; vsh[tx] = vv;
                taus[tx] -= 0.1f * (mm * bc1p) / (sqrtf(vv * bc2p) + 1e-8f);
            }
        }
        if (Q < 2 && U < NM) {
            sreg = sigm(gl);
            (Q ? GnbF : GnaF)[U] = -2.f * sreg;
        }
        // zero NEXT-write slots (distinct from read/write slots; all prior
        // readers of slot zs arrived at head t-1, which we just waited on)
        if (tx < 256) g_S2buf[zs][tx] = 0.f;
        if (tx == 256 + 0 && b == 0) { }   // placeholder keep lanes busy
        if (tx == 0) g_Lbuf[zs] = (b == 0) ? g_Lbuf[zs] * 0.f : g_Lbuf[zs];
        if (tx == 0 && b == 0) g_Lbuf[zs] = 0.f;
        __syncthreads();   // syncA: taus + Gn + lsh published
        if (t >= 2 && !stop && lsh < 1e-3f) stop = 1;

        // head posts: S1 row sums + S2 contributions from taus(t), G(t)
        if (!stop) {
            float w = 0.f;
            if (Q < 2 && U < NM)
                w = sreg * fmaxf(taus[Q ? r1 : r0] - taus[16 + U] + 0.1f, 0.f);
            WRED(w, wsum2);
            if (tx >= 16 && tx < 256) {
                const int m = tx;
                float e0 = fmaxf(taus[r0] - taus[m] + 0.1f, 0.f);
                float e1 = fmaxf(taus[r1] - taus[m] + 0.1f, 0.f);
                float c = (-0.5f * GnaF[m - 16]) * e0 + (-0.5f * GnbF[m - 16]) * e1;
                redadd(&g_S2buf[cs][m], c);
            }
        }
        __threadfence();
        __syncthreads();   // syncB: wsum2 published + zero stores + reds fenced
        if (tx == 0) {
            if (!stop) {
                redadd(&g_S2buf[cs][r0], -sum8(wsum2, 0));
                redadd(&g_S2buf[cs][r1], -sum8(wsum2, 1));
                __threadfence();
            }
            atomicAdd(&g_gc[cs], 1u);   // arrive (unconditional)
        }

        // ================= BODY (overlaps other blocks' heads) =================
        if (!stop) {
            if (U < NM) {
                const int j = U;
                const ulonglong2* ap = At8 + (15 * Q) * NM + j;
                ulonglong2 an = ap[0];
                u64 pa0 = ONES2, pa1 = ONES2, pb0 = ONES2, pb1 = ONES2;
                #pragma unroll 5
                for (int c = 0; c < 15; ++c) {
                    ulonglong2 a = an;
                    if (c < 14) an = ap[(c + 1) * NM];
                    ulonglong2 ga = GnaP2[15 * Q + c];
                    ulonglong2 gb = GnbP2[15 * Q + c];
                    pa0 = mul2_(pa0, fma2_(a.x, ga.x, ONES2));
                    pa1 = mul2_(pa1, fma2_(a.y, ga.y, ONES2));
                    pb0 = mul2_(pb0, fma2_(a.x, gb.x, ONES2));
                    pb1 = mul2_(pb1, fma2_(a.y, gb.y, ONES2));
                }
                F2 x0; x0.u = pa0; F2 x1; x1.u = pa1;
                pfA[Q * NM + j] = (x0.f.x * x0.f.y) * (x1.f.x * x1.f.y);
                x0.u = pb0; x1.u = pb1;
                pfB[Q * NM + j] = (x0.f.x * x0.f.y) * (x1.f.x * x1.f.y);
            }
            __syncthreads();

            float v = 0.f;
            int nz = 0;
            if (U < NM) {
                const int j = U;
                if (Q == 0) {
                    float P = (pfA[j] * pfA[NM + j]) * (pfA[2 * NM + j] * pfA[3 * NM + j]);
                    float e = P - ((j == r0) ? -1.f : 1.f);
                    v = e * e;
                    float ds = e * P * (1.f / 480.f);
                    ((float*)DsA4)[j] = ds;
                    nz = (ds != 0.f);
                } else if (Q == 1) {
                    float P = (pfB[j] * pfB[NM + j]) * (pfB[2 * NM + j] * pfB[3 * NM + j]);
                    float e = P - ((j == r1) ? -1.f : 1.f);
                    v = e * e;
                    float ds = e * P * (1.f / 480.f);
                    ((float*)DsB4)[j] = ds;
                    nz = (ds != 0.f);
                } else if (Q == 2) {
                    float d = fmaxf(taus[r0] - taus[16 + j] + 0.1f, 0.f);
                    v = (-0.5f * GnaF[j]) * d * d;
                } else {
                    float d = fmaxf(taus[r1] - taus[16 + j] + 0.1f, 0.f);
                    v = (-0.5f * GnbF[j]) * d * d;
                }
            }
            WRED(v, wsum);
            int anyNZ = __syncthreads_or(nz);
            if (tx == 0) {
                float la = sum8(wsum, 0), lb = sum8(wsum, 1);
                float lo = sum8(wsum, 2) + sum8(wsum, 3);
                redadd(&g_Lbuf[cs], (la + lb) * (1.f / 960.f) + lo * (1.f / 61440.f));
            }

            if (anyNZ) {   // backward only if any Ds nonzero (P underflows in fp32)
                if (U < NM) {
                    const int k = U;
                    F2 gp; gp.f.x = GnaF[k]; gp.f.y = GnaF[k];
                    const u64 gna2 = gp.u;
                    gp.f.x = GnbF[k]; gp.f.y = GnbF[k];
                    const u64 gnb2 = gp.u;
                    float accA = 0.f, accB = 0.f;
                    bool bad = false;
                    const ulonglong2* abp = Ab8 + (15 * Q) * NM + k;
                    ulonglong2 an = abp[0];
                    #pragma unroll 5
                    for (int c = 0; c < 15; ++c) {
                        ulonglong2 a = an;
                        if (c < 14) an = abp[(c + 1) * NM];
                        ulonglong2 dA = DsA8[15 * Q + c];
                        ulonglong2 dB = DsB8[15 * Q + c];
                        u64 t01 = fma2_(a.x, gna2, ONES2);
                        u64 t23 = fma2_(a.y, gna2, ONES2);
                        u64 n01 = mul2_(dA.x, a.x);
                        u64 n23 = mul2_(dA.y, a.y);
                        QUADACC(t01, t23, n01, n23, accA, bad);
                        t01 = fma2_(a.x, gnb2, ONES2);
                        t23 = fma2_(a.y, gnb2, ONES2);
                        n01 = mul2_(dB.x, a.x);
                        n23 = mul2_(dB.y, a.y);
                        QUADACC(t01, t23, n01, n23, accB, bad);
                    }
                    if (bad) {
                        accA = 0.f; accB = 0.f;
                        const float gna = GnaF[k], gnb = GnbF[k];
                        for (int c = 0; c < 15; ++c) {
                            int jb = 15 * Q + c;
                            float4 a4 = g_Ab4[jb * NM + k];
                            float4 dA = DsA4[jb], dB = DsB4[jb];
                            const float* av = (const float*)&a4;
                            const float* dv = (const float*)&dA;
                            const float* ev = (const float*)&dB;
                            #pragma unroll
                            for (int e2 = 0; e2 < 4; ++e2) {
                                float tA = fmaf(av[e2], gna, 1.f);
                                float tB = fmaf(av[e2], gnb, 1.f);
                                accA += (tA != 0.f) ? __fdividef(dv[e2] * av[e2], tA) : 0.f;
                                accB += (tB != 0.f) ? __fdividef(ev[e2] * av[e2], tB) : 0.f;
                            }
                        }
                    }
                    pfA[Q * NM + k] = accA;
                    pfB[Q * NM + k] = accB;
                }
                __syncthreads();
            }

            if (Q < 2 && U < NM) {   // Adam(G), step t
                const int k = U;
                float S = 0.f;
                if (anyNZ) {
                    const float* pf = Q ? pfB : pfA;
                    S = (pf[k] + pf[NM + k]) + (pf[2 * NM + k] + pf[3 * NM + k]);
                }
                float s = -0.5f * (Q ? GnbF : GnaF)[k];
                float d = fmaxf(taus[Q ? r1 : r0] - taus[16 + k] + 0.1f, 0.f);
                float grad = (-2.f * S + d * d * (1.f / 61440.f)) * (s * (1.f - s));
                mg = 0.9f * mg + 0.1f * grad;
                vg = 0.999f * vg + 0.001f * grad * grad;
                gl -= 0.1f * (mg * bc1c) / (sqrtf(vg * bc2c) + 1e-8f);
            }
        }
        bc1p = bc1c; bc2p = bc2c;
    }

    // ---- final tau update (Adam step 29): slot 29&3 = 1 fully posted ----
    {
        unsigned tgt = gbase[1] + 960u;
        if (tx == 0) { while (ld_acq(&g_gc[1]) < tgt) __nanosleep(32); }
        __syncthreads();
        float s = (tx < 256) ? ldcg(&g_S2buf[1][tx]) : 0.f;
        if (!stop && tx < 256) {
            float g = -(2.f / 61440.f) * s;
            float mm = 0.9f * msh[tx] + 0.1f * g;
            float vv = 0.999f * vsh[tx] + 0.001f * g * g;
            taus[tx] -= 0.1f * (mm * bc1p) / (sqrtf(vv * bc2p) + 1e-8f);
        }
        __syncthreads();
    }

    // ---- epilogue: final loss at p_final ----
    if (Q < 2 && U < NM) (Q ? GnbF : GnaF)[U] = -2.f * sigm(gl);
    __syncthreads();
    if (U < NM) {
        const int j = U;
        const ulonglong2* ap = At8 + (15 * Q) * NM + j;
        ulonglong2 an = ap[0];
        u64 pa0 = ONES2, pa1 = ONES2, pb0 = ONES2, pb1 = ONES2;
        #pragma unroll 5
        for (int c = 0; c < 15; ++c) {
            ulonglong2 a = an;
            if (c < 14) an = ap[(c + 1) * NM];
            ulonglong2 ga = GnaP2[15 * Q + c];
            ulonglong2 gb = GnbP2[15 * Q + c];
            pa0 = mul2_(pa0, fma2_(a.x, ga.x, ONES2));
            pa1 = mul2_(pa1, fma2_(a.y, ga.y, ONES2));
            pb0 = mul2_(pb0, fma2_(a.x, gb.x, ONES2));
            pb1 = mul2_(pb1, fma2_(a.y, gb.y, ONES2));
        }
        F2 x0; x0.u = pa0; F2 x1; x1.u = pa1;
        pfA[Q * NM + U] = (x0.f.x * x0.f.y) * (x1.f.x * x1.f.y);
        x0.u = pb0; x1.u = pb1;
        pfB[Q * NM + U] = (x0.f.x * x0.f.y) * (x1.f.x * x1.f.y);
    }
    __syncthreads();
    {
        float v = 0.f;
        if (U < NM) {
            const int j = U;
            if (Q == 0) {
                float P = (pfA[j] * pfA[NM + j]) * (pfA[2 * NM + j] * pfA[3 * NM + j]);
                float e = P - ((j == r0) ? -1.f : 1.f);
                v = e * e;
            } else if (Q == 1) {
                float P = (pfB[j] * pfB[NM + j]) * (pfB[2 * NM + j] * pfB[3 * NM + j]);
                float e = P - ((j == r1) ? -1.f : 1.f);
                v = e * e;
            } else if (Q == 2) {
                float d = fmaxf(taus[r0] - taus[16 + j] + 0.1f, 0.f);
                v = (-0.5f * GnaF[j]) * d * d;
            } else {
                float d = fmaxf(taus[r1] - taus[16 + j] + 0.1f, 0.f);
                v = (-0.5f * GnbF[j]) * d * d;
            }
        }
        WRED(v, wsum);
        __syncthreads();
        if (tx == 0) {
            float la = sum8(wsum, 0), lb = sum8(wsum, 1);
            float lo = sum8(wsum, 2) + sum8(wsum, 3);
            g_Lp[b] = (la + lb) * (1.f / 960.f) + lo * (1.f / 61440.f);
        }
    }
    GRIDBAR();  // barrier #2
    if (b == 0) {
        float lv = 0.f;
        if (tx < 30) {
            float4 q = ldcg4(((const float4*)g_Lp) + tx);
            lv = (q.x + q.y) + (q.z + q.w);
        }
        if (tx < 32) {
            lv += __shfl_down_sync(0xffffffffu, lv, 16);
            lv += __shfl_down_sync(0xffffffffu, lv, 8);
            lv += __shfl_down_sync(0xffffffffu, lv, 4);
            lv += __shfl_down_sync(0xffffffffu, lv, 2);
            lv += __shfl_down_sync(0xffffffffu, lv, 1);
            if (tx == 0) out[0] = lv;
        }
        // leave S2/L slots dirty: next launch's init (b==0) re-zeroes them
        if (tx < 1024) ((float*)g_S2buf)[tx] = ((float*)g_S2buf)[tx] * 0.f;
        if (tx < 4) g_Lbuf[tx] = 0.f;
    }
}

// ---------------- launch ----------------
extern "C" void kernel_launch(void* const* d_in, const int* in_sizes, int n_in,
                              void* d_out, int out_size) {
    const float* A    = (const float*)d_in[0];
    const float* Gl0  = (const float*)d_in[1];
    const float* tau0 = (const float*)d_in[2];
    gflow<<<NB, 1024>>>(A, Gl0, tau0, (float*)d_out);
}

// round 16
// speedup vs baseline: 1.1504x; 1.1504x over previous
#include <cuda_runtime.h>
#include <math.h>

#define NN 256
#define NM 240
#define NB 240
#define NT 512
#define ITERS 30
#define PER_LAUNCH (2 * NB)

typedef unsigned long long u64;
union F2 { u64 u; float2 f; };
#define ONES2 0x3f8000003f800000ULL

// ---------------- device scratch ----------------
__device__ float4   g_At4[60 * NM];    // [kb*240+j] = A[j][16+4kb..16+4kb+3]
__device__ float4   g_Ab4[60 * NM];    // [jb*240+k] = A[4jb+r][16+k]
__device__ float    g_S2buf[4][256];   // 4-slot tau-grad accumulators
__device__ float    g_Lbuf[4];         // 4-slot loss accumulators
__device__ float    g_Lp[256];         // epilogue per-block loss partials
__device__ unsigned g_gc[4];           // per-slot head-arrival counters
__device__ unsigned g_barcnt;

// ---------------- helpers ----------------
static __device__ __forceinline__ unsigned ld_acq(const unsigned* p) {
    unsigned v; asm volatile("ld.acquire.gpu.global.u32 %0,[%1];" : "=r"(v) : "l"(p)); return v;
}
static __device__ __forceinline__ float ldcg(const float* p) {
    float v; asm volatile("ld.global.cg.f32 %0,[%1];" : "=f"(v) : "l"(p)); return v;
}
static __device__ __forceinline__ float4 ldcg4(const float4* p) {
    float4 v;
    asm volatile("ld.global.cg.v4.f32 {%0,%1,%2,%3},[%4];"
                 : "=f"(v.x), "=f"(v.y), "=f"(v.z), "=f"(v.w) : "l"(p));
    return v;
}
static __device__ __forceinline__ void redadd(float* p, float v) {
    asm volatile("red.global.add.f32 [%0],%1;" :: "l"(p), "f"(v) : "memory");
}
static __device__ __forceinline__ float rcpa(float x) {
    float r; asm("rcp.approx.f32 %0,%1;" : "=f"(r) : "f"(x)); return r;
}
static __device__ __forceinline__ u64 fma2_(u64 a, u64 b, u64 c) {
    u64 d; asm("fma.rn.f32x2 %0,%1,%2,%3;" : "=l"(d) : "l"(a), "l"(b), "l"(c)); return d;
}
static __device__ __forceinline__ u64 mul2_(u64 a, u64 b) {
    u64 d; asm("mul.rn.f32x2 %0,%1,%2;" : "=l"(d) : "l"(a), "l"(b)); return d;
}
static __device__ __forceinline__ float sigm(float x) { return 1.0f / (1.0f + __expf(-x)); }

// 512-thread warp-leader reduce: dst[warp] for 16 warps
#define WRED(val, dst) do { float _v = (val);                             \
    _v += __shfl_down_sync(0xffffffffu, _v, 16);                          \
    _v += __shfl_down_sync(0xffffffffu, _v, 8);                           \
    _v += __shfl_down_sync(0xffffffffu, _v, 4);                           \
    _v += __shfl_down_sync(0xffffffffu, _v, 2);                           \
    _v += __shfl_down_sync(0xffffffffu, _v, 1);                           \
    if ((tx & 31) == 0) (dst)[tx >> 5] = _v; } while (0)

static __device__ __forceinline__ float sum8(const float* w, int g) {
    float s = 0.f;
    #pragma unroll
    for (int i = 0; i < 8; ++i) s += w[g * 8 + i];
    return s;
}

#define GRIDBAR() do { __syncthreads();                                   \
    if (tx == 0) { __threadfence(); atomicAdd(&g_barcnt, 1u);             \
        while (ld_acq(&g_barcnt) < bartgt) __nanosleep(32); }             \
    bartgt += NB; __syncthreads(); } while (0)

#define QUADACC(t01u, t23u, n01u, n23u, acc, bad) do {                    \
    F2 _t0; _t0.u = (t01u); F2 _t1; _t1.u = (t23u);                       \
    F2 _n0; _n0.u = (n01u); F2 _n1; _n1.u = (n23u);                       \
    float _P01 = _t0.f.x * _t0.f.y;                                       \
    float _P23 = _t1.f.x * _t1.f.y;                                       \
    float _T = _P01 * _P23;                                               \
    float _r = rcpa(_T);                                                  \
    float _m1 = fmaf(_n0.f.y, _t0.f.x, _n0.f.x * _t0.f.y);                \
    float _m3 = fmaf(_n1.f.y, _t1.f.x, _n1.f.x * _t1.f.y);                \
    float _s = fmaf(_m3, _P01, _m1 * _P23);                               \
    bool _ok = (_T != 0.f);                                               \
    acc += _ok ? _s * _r : 0.f;                                           \
    bad |= !_ok; } while (0)

// ---------------- persistent kernel: 240 blocks x 512 thr, 1 row/block ----
__global__ void __launch_bounds__(NT, 2) gflow(
    const float* __restrict__ A, const float* __restrict__ Gl0,
    const float* __restrict__ tau0, float* __restrict__ out)
{
    const int b  = blockIdx.x;     // row r = b
    const int tx = threadIdx.x;
    const int H  = tx >> 8;        // k/j half 0..1
    const int U  = tx & 255;
    const int r  = b;

    __shared__ u64   GnP[120];            // -2*sigmoid(Gl[r][.]) packed
    __shared__ float4 Ds4[60];            // (P-T)*P/480
    __shared__ float pf[2 * NM];          // half partials
    __shared__ float taus[NN];
    __shared__ float msh[NN], vsh[NN];    // replicated tau-Adam state
    __shared__ float wsum[16], wsum2[16];
    __shared__ float lsh;
    float* GnF = (float*)GnP;
    const ulonglong2* At8 = (const ulonglong2*)g_At4;
    const ulonglong2* Ab8 = (const ulonglong2*)g_Ab4;
    const ulonglong2* Ds8 = (const ulonglong2*)Ds4;
    const ulonglong2* GnP2 = (const ulonglong2*)GnP;

    unsigned bartgt = (ld_acq(&g_barcnt) / PER_LAUNCH) * PER_LAUNCH + NB;
    unsigned gbase[4];
    gbase[0] = (ld_acq(&g_gc[0]) / 1920u) * 1920u;
    gbase[1] = (ld_acq(&g_gc[1]) / 1920u) * 1920u;
    gbase[2] = (ld_acq(&g_gc[2]) / 1680u) * 1680u;
    gbase[3] = (ld_acq(&g_gc[3]) / 1680u) * 1680u;

    // ---- init: repack A (60 float4 entries per block per layout) ----
    if (tx < 60) {
        int e = b * 60 + tx, kb = e / NM, j = e % NM;
        g_At4[e] = *(const float4*)(A + j * NN + 16 + 4 * kb);
        float4 v;
        v.x = A[(4 * kb + 0) * NN + 16 + j];
        v.y = A[(4 * kb + 1) * NN + 16 + j];
        v.z = A[(4 * kb + 2) * NN + 16 + j];
        v.w = A[(4 * kb + 3) * NN + 16 + j];
        g_Ab4[e] = v;
    }
    if (b == 0) {
        ((float*)g_S2buf)[tx] = 0.f;
        ((float*)g_S2buf)[tx + 512] = 0.f;
        if (tx < 4) g_Lbuf[tx] = 0.f;
    }
    float gl = 0.f, mg = 0.f, vg = 0.f;     // Adam state for Gl[r][U] (H==0)
    if (H == 0 && U < NM) gl = Gl0[r * NM + U];
    if (tx < NN) { taus[tx] = tau0[tx]; msh[tx] = 0.f; vsh[tx] = 0.f; }
    GRIDBAR();  // barrier #1

    double b1t = 1.0, b2t = 1.0;
    float bc1p = 1.f, bc2p = 1.f;
    int stop = 0;

    for (int t = 0; t < ITERS; ++t) {
        b1t *= 0.9; b2t *= 0.999;
        const float bc1c = (float)(1.0 / (1.0 - b1t));
        const float bc2c = (float)(1.0 / (1.0 - b2t));
        const int cs = t & 3;
        const int zs = (t + 1) & 3;

        // ================= HEAD =================
        if (t > 0) {
            const int ws = (t - 1) & 3;
            unsigned tgt = gbase[ws] + ((unsigned)((t - 1) >> 2) + 1u) * (unsigned)NB;
            if (tx == 0) { while (ld_acq(&g_gc[ws]) < tgt) __nanosleep(32); }
            __syncthreads();
            float s2v = 0.f;
            if (tx < 256) s2v = ldcg(&g_S2buf[ws][tx]);                 // READ ONLY
            if (t >= 2 && tx == 0) lsh = ldcg(&g_Lbuf[(t - 2) & 3]);    // READ ONLY
            if (!stop && tx < 256) {   // replicated tau Adam, step t-1
                float g = -(2.f / 61440.f) * s2v;
                float mm = 0.9f * msh[tx] + 0.1f * g;
                float vv = 0.999f * vsh[tx] + 0.001f * g * g;
                msh[tx] = mm; vsh[tx] = vv;
                taus[tx] -= 0.1f * (mm * bc1p) / (sqrtf(vv * bc2p) + 1e-8f);
            }
        }
        if (H == 0 && U < NM) GnF[U] = -2.f * sigm(gl);
        if (tx < 256) g_S2buf[zs][tx] = 0.f;     // zero next-write slot (safe)
        if (tx == 0 && b == 0) g_Lbuf[zs] = 0.f;
        __syncthreads();   // syncA: taus + Gn + lsh published
        if (t >= 2 && !stop && lsh < 1e-3f) stop = 1;

        // head posts: S1 row sum (H1) + S2 contributions
        if (!stop) {
            float w = 0.f;
            if (H == 1 && U < NM)
                w = (-0.5f * GnF[U]) * fmaxf(taus[r] - taus[16 + U] + 0.1f, 0.f);
            WRED(w, wsum2);
            if (tx >= 16 && tx < 256) {
                const int m = tx;
                float e0 = fmaxf(taus[r] - taus[m] + 0.1f, 0.f);
                redadd(&g_S2buf[cs][m], (-0.5f * GnF[m - 16]) * e0);
            }
        }
        __threadfence();
        __syncthreads();   // syncB
        if (tx == 0) {
            if (!stop) {
                redadd(&g_S2buf[cs][r], -sum8(wsum2, 1));   // -S1[r]
                __threadfence();
            }
            atomicAdd(&g_gc[cs], 1u);   // arrive (unconditional)
        }

        // ================= BODY =================
        if (!stop) {
            // forward: thread (H, j=U) -> product over k-half H
            if (U < NM) {
                const ulonglong2* ap = At8 + (30 * H) * NM + U;
                ulonglong2 an = ap[0];
                u64 p0 = ONES2, p1 = ONES2;
                #pragma unroll 6
                for (int c = 0; c < 30; ++c) {
                    ulonglong2 a = an;
                    if (c < 29) an = ap[(c + 1) * NM];
                    ulonglong2 ga = GnP2[30 * H + c];
                    p0 = mul2_(p0, fma2_(a.x, ga.x, ONES2));
                    p1 = mul2_(p1, fma2_(a.y, ga.y, ONES2));
                }
                F2 x0; x0.u = p0; F2 x1; x1.u = p1;
                pf[H * NM + U] = (x0.f.x * x0.f.y) * (x1.f.x * x1.f.y);
            }
            __syncthreads();

            float v = 0.f;
            int nz = 0;
            if (U < NM) {
                if (H == 0) {
                    float P = pf[U] * pf[NM + U];
                    float e = P - ((U == r) ? -1.f : 1.f);
                    v = e * e;   // la
                    float ds = e * P * (1.f / 480.f);
                    ((float*)Ds4)[U] = ds;
                    nz = (ds != 0.f);
                } else {
                    float d = fmaxf(taus[r] - taus[16 + U] + 0.1f, 0.f);
                    v = (-0.5f * GnF[U]) * d * d;   // lo
                }
            }
            WRED(v, wsum);
            int anyNZ = __syncthreads_or(nz);
            if (tx == 0)
                redadd(&g_Lbuf[cs], sum8(wsum, 0) * (1.f / 960.f)
                                  + sum8(wsum, 1) * (1.f / 61440.f));

            // backward only if any Ds nonzero (P underflows to 0 in fp32)
            if (anyNZ) {
                if (U < NM) {
                    const int k = U;
                    F2 gp; gp.f.x = GnF[k]; gp.f.y = GnF[k];
                    const u64 gn2 = gp.u;
                    float acc = 0.f;
                    bool bad = false;
                    const ulonglong2* abp = Ab8 + (30 * H) * NM + k;
                    ulonglong2 an = abp[0];
                    #pragma unroll 6
                    for (int c = 0; c < 30; ++c) {
                        ulonglong2 a = an;
                        if (c < 29) an = abp[(c + 1) * NM];
                        ulonglong2 dA = Ds8[30 * H + c];
                        u64 t01 = fma2_(a.x, gn2, ONES2);
                        u64 t23 = fma2_(a.y, gn2, ONES2);
                        u64 n01 = mul2_(dA.x, a.x);
                        u64 n23 = mul2_(dA.y, a.y);
                        QUADACC(t01, t23, n01, n23, acc, bad);
                    }
                    if (bad) {   // exact-zero term: safe redo (rare)
                        acc = 0.f;
                        const float gn = GnF[k];
                        for (int c = 0; c < 30; ++c) {
                            int jb = 30 * H + c;
                            float4 a4 = g_Ab4[jb * NM + k];
                            float4 dA = Ds4[jb];
                            const float* av = (const float*)&a4;
                            const float* dv = (const float*)&dA;
                            #pragma unroll
                            for (int e2 = 0; e2 < 4; ++e2) {
                                float tA = fmaf(av[e2], gn, 1.f);
                                acc += (tA != 0.f) ? __fdividef(dv[e2] * av[e2], tA) : 0.f;
                            }
                        }
                    }
                    pf[H * NM + k] = acc;
                }
                __syncthreads();
            }

            // Adam(G), step t  (S == 0 exactly when backward skipped)
            if (H == 0 && U < NM) {
                const int k = U;
                float S = anyNZ ? (pf[k] + pf[NM + k]) : 0.f;
                float s = -0.5f * GnF[k];
                float d = fmaxf(taus[r] - taus[16 + k] + 0.1f, 0.f);
                float grad = (-2.f * S + d * d * (1.f / 61440.f)) * (s * (1.f - s));
                mg = 0.9f * mg + 0.1f * grad;
                vg = 0.999f * vg + 0.001f * grad * grad;
                gl -= 0.1f * (mg * bc1c) / (sqrtf(vg * bc2c) + 1e-8f);
            }
        }
        bc1p = bc1c; bc2p = bc2c;
    }

    // ---- final tau update (Adam step 29): slot 1 fully posted ----
    {
        unsigned tgt = gbase[1] + 1920u;
        if (tx == 0) { while (ld_acq(&g_gc[1]) < tgt) __nanosleep(32); }
        __syncthreads();
        float s = (tx < 256) ? ldcg(&g_S2buf[1][tx]) : 0.f;
        if (!stop && tx < 256) {
            float g = -(2.f / 61440.f) * s;
            float mm = 0.9f * msh[tx] + 0.1f * g;
            float vv = 0.999f * vsh[tx] + 0.001f * g * g;
            taus[tx] -= 0.1f * (mm * bc1p) / (sqrtf(vv * bc2p) + 1e-8f);
        }
        __syncthreads();
    }

    // ---- epilogue: final loss at p_final ----
    if (H == 0 && U < NM) GnF[U] = -2.f * sigm(gl);
    __syncthreads();
    if (U < NM) {
        const ulonglong2* ap = At8 + (30 * H) * NM + U;
        ulonglong2 an = ap[0];
        u64 p0 = ONES2, p1 = ONES2;
        #pragma unroll 6
        for (int c = 0; c < 30; ++c) {
            ulonglong2 a = an;
            if (c < 29) an = ap[(c + 1) * NM];
            ulonglong2 ga = GnP2[30 * H + c];
            p0 = mul2_(p0, fma2_(a.x, ga.x, ONES2));
            p1 = mul2_(p1, fma2_(a.y, ga.y, ONES2));
        }
        F2 x0; x0.u = p0; F2 x1; x1.u = p1;
        pf[H * NM + U] = (x0.f.x * x0.f.y) * (x1.f.x * x1.f.y);
    }
    __syncthreads();
    {
        float v = 0.f;
        if (U < NM) {
            if (H == 0) {
                float P = pf[U] * pf[NM + U];
                float e = P - ((U == r) ? -1.f : 1.f);
                v = e * e;
            } else {
                float d = fmaxf(taus[r] - taus[16 + U] + 0.1f, 0.f);
                v = (-0.5f * GnF[U]) * d * d;
            }
        }
        WRED(v, wsum);
        __syncthreads();
        if (tx == 0)
            g_Lp[b] = sum8(wsum, 0) * (1.f / 960.f) + sum8(wsum, 1) * (1.f / 61440.f);
    }
    GRIDBAR();  // barrier #2
    if (b == 0) {
        float lv = 0.f;
        if (tx < 60) {
            float4 q = ldcg4(((const float4*)g_Lp) + tx);
            lv = (q.x + q.y) + (q.z + q.w);
        }
        WRED(lv, wsum);
        __syncthreads();
        if (tx == 0) out[0] = wsum[0] + wsum[1];
    }
}

// ---------------- launch ----------------
extern "C" void kernel_launch(void* const* d_in, const int* in_sizes, int n_in,
                              void* d_out, int out_size) {
    const float* A    = (const float*)d_in[0];
    const float* Gl0  = (const float*)d_in[1];
    const float* tau0 = (const float*)d_in[2];
    gflow<<<NB, NT>>>(A, Gl0, tau0, (float*)d_out);
}